// round 13
// baseline (speedup 1.0000x reference)
#include <cuda_runtime.h>

#define BB 256
#define TT 50
#define MM 20
#define EE 128
#define G3 384
#define NS 40            // single-row CTAs (longest rows)
#define GRID 148         // NS + (256-NS)/2

typedef unsigned long long u64;

// scratch (no cudaMalloc allowed)
__device__ __align__(16) float g_ub[BB*TT*EE];   // basket means (B,T,E)
__device__ __align__(16) float g_xg[BB*TT*G3];   // input gates  (B,T,3E)

__device__ __forceinline__ void fma2(u64 &acc, u64 a, u64 b){
    asm("fma.rn.f32x2 %0, %1, %2, %0;" : "+l"(acc) : "l"(a), "l"(b));
}
__device__ __forceinline__ u64 add2(u64 a, u64 b){
    u64 r; asm("add.rn.f32x2 %0, %1, %2;" : "=l"(r) : "l"(a), "l"(b));
    return r;
}
__device__ __forceinline__ float hsum2(u64 v){
    float lo, hi;
    asm("mov.b64 {%0,%1}, %2;" : "=f"(lo), "=f"(hi) : "l"(v));
    return lo + hi;
}
__device__ __forceinline__ float sigf(float x){
    return __fdividef(1.f, 1.f + __expf(-x));
}
__device__ __forceinline__ float tanhfast(float x){
    return __fdividef(2.f, 1.f + __expf(-2.f*x)) - 1.f;
}

// dot of this thread's W row with a 128-float vector in SMEM (broadcast LDS)
__device__ __forceinline__ float dot_s(const u64* __restrict__ w,
                                       const float* __restrict__ src){
    u64 ca = 0ull, cb = 0ull;
    const ulonglong2* hp = (const ulonglong2*)src;
    #pragma unroll
    for (int k = 0; k < 32; ++k){
        ulonglong2 v = hp[k];
        fma2(ca, w[2*k  ], v.x);
        fma2(cb, w[2*k+1], v.y);
    }
    return hsum2(add2(ca, cb));
}

// ---------------------------------------------------------------------------
// K1: gather (measured ~5us, unchanged)
// ---------------------------------------------------------------------------
#define RED20(FLD) \
    ((((v[0].FLD+v[1].FLD)+(v[2].FLD+v[3].FLD))+((v[4].FLD+v[5].FLD)+(v[6].FLD+v[7].FLD))) \
    +(((v[8].FLD+v[9].FLD)+(v[10].FLD+v[11].FLD))+((v[12].FLD+v[13].FLD)+(v[14].FLD+v[15].FLD))) \
    +((v[16].FLD+v[17].FLD)+(v[18].FLD+v[19].FLD)))

__global__ void __launch_bounds__(128,2) k_gather(const int* __restrict__ ids,
                                                  const int* __restrict__ bsz,
                                                  const int* __restrict__ lens,
                                                  const float* __restrict__ emb){
    const int p    = blockIdx.x * 4 + (threadIdx.x >> 5);   // 0..6399
    const int lane = threadIdx.x & 31;
    const float4* e4 = (const float4*)emb;

    const int r0 = p, r1 = 12799 - p;
    const int b0g = r0 / TT, t0g = r0 - b0g*TT;
    const int b1g = r1 / TT, t1g = r1 - b1g*TT;
    const bool act0 = t0g < __ldg(lens + b0g);
    const bool act1 = t1g < __ldg(lens + b1g);

    float4 v[20], u[20];
    if (act0){
        const int4* ip = (const int4*)(ids + r0*MM);
        const int4 i0=__ldg(ip), i1=__ldg(ip+1), i2=__ldg(ip+2),
                   i3=__ldg(ip+3), i4=__ldg(ip+4);
        v[0]=__ldg(e4+i0.x*32+lane);  v[1]=__ldg(e4+i0.y*32+lane);
        v[2]=__ldg(e4+i0.z*32+lane);  v[3]=__ldg(e4+i0.w*32+lane);
        v[4]=__ldg(e4+i1.x*32+lane);  v[5]=__ldg(e4+i1.y*32+lane);
        v[6]=__ldg(e4+i1.z*32+lane);  v[7]=__ldg(e4+i1.w*32+lane);
        v[8]=__ldg(e4+i2.x*32+lane);  v[9]=__ldg(e4+i2.y*32+lane);
        v[10]=__ldg(e4+i2.z*32+lane); v[11]=__ldg(e4+i2.w*32+lane);
        v[12]=__ldg(e4+i3.x*32+lane); v[13]=__ldg(e4+i3.y*32+lane);
        v[14]=__ldg(e4+i3.z*32+lane); v[15]=__ldg(e4+i3.w*32+lane);
        v[16]=__ldg(e4+i4.x*32+lane); v[17]=__ldg(e4+i4.y*32+lane);
        v[18]=__ldg(e4+i4.z*32+lane); v[19]=__ldg(e4+i4.w*32+lane);
    }
    if (act1){
        const int4* ip = (const int4*)(ids + r1*MM);
        const int4 i0=__ldg(ip), i1=__ldg(ip+1), i2=__ldg(ip+2),
                   i3=__ldg(ip+3), i4=__ldg(ip+4);
        u[0]=__ldg(e4+i0.x*32+lane);  u[1]=__ldg(e4+i0.y*32+lane);
        u[2]=__ldg(e4+i0.z*32+lane);  u[3]=__ldg(e4+i0.w*32+lane);
        u[4]=__ldg(e4+i1.x*32+lane);  u[5]=__ldg(e4+i1.y*32+lane);
        u[6]=__ldg(e4+i1.z*32+lane);  u[7]=__ldg(e4+i1.w*32+lane);
        u[8]=__ldg(e4+i2.x*32+lane);  u[9]=__ldg(e4+i2.y*32+lane);
        u[10]=__ldg(e4+i2.z*32+lane); u[11]=__ldg(e4+i2.w*32+lane);
        u[12]=__ldg(e4+i3.x*32+lane); u[13]=__ldg(e4+i3.y*32+lane);
        u[14]=__ldg(e4+i3.z*32+lane); u[15]=__ldg(e4+i3.w*32+lane);
        u[16]=__ldg(e4+i4.x*32+lane); u[17]=__ldg(e4+i4.y*32+lane);
        u[18]=__ldg(e4+i4.z*32+lane); u[19]=__ldg(e4+i4.w*32+lane);
    }
    if (act0){
        const float inv = 1.0f / (float)__ldg(bsz + r0);
        float4 a;
        a.x = RED20(x)*inv; a.y = RED20(y)*inv; a.z = RED20(z)*inv; a.w = RED20(w)*inv;
        ((float4*)g_ub)[r0*32 + lane] = a;
    }
    if (act1){
        #pragma unroll
        for (int k = 0; k < 20; ++k) v[k] = u[k];
        const float inv = 1.0f / (float)__ldg(bsz + r1);
        float4 a;
        a.x = RED20(x)*inv; a.y = RED20(y)*inv; a.z = RED20(z)*inv; a.w = RED20(w)*inv;
        ((float4*)g_ub)[r1*32 + lane] = a;
    }
}

// ---------------------------------------------------------------------------
// K2: xg. Singles+pairs flat job list (R12 phase-B code), writes g_xg.
//   bid <  NS : single row  b0 = bid              (len1 = 0)
//   bid >= NS : pair  b0 = bid, b1 = 255+NS-bid
// ---------------------------------------------------------------------------
__global__ void __launch_bounds__(384,1) k_xg(
    const float* __restrict__ W_ih,
    const float* __restrict__ b_ih,
    const int*   __restrict__ lens)
{
    __shared__ __align__(16) float s_ub[4*EE];   // quad buffer

    const int j   = threadIdx.x;
    const int bid = blockIdx.x;
    const bool dual = (bid >= NS);
    const int b0 = bid;
    const int b1 = dual ? (255 + NS - bid) : bid;
    const int len0 = __ldg(lens + b0);
    const int len1 = dual ? __ldg(lens + b1) : 0;
    const int total = len0 + len1;

    u64 w[64];
    {
        const u64* wr = (const u64*)(W_ih + j*EE);
        #pragma unroll
        for (int k = 0; k < 64; ++k) w[k] = __ldg(wr + k);
    }
    const float bi = __ldg(b_ih + j);
    const int lane = j & 31, lw = j >> 5;

    if (lw < 2 && lw < total){                   // preload jobs 0,1
        const int rsel = (lw >= len0);
        const int t    = lw - (rsel ? len0 : 0);
        const int bb   = rsel ? b1 : b0;
        ((float4*)(s_ub + (lw & 3)*EE))[lane] =
            ((const float4*)(g_ub + (bb*TT + t)*EE))[lane];
    }
    __syncthreads();

    for (int i = 0; i < total; i += 2){
        float4 pf; bool hav = false;
        if (lw < 2){
            const int ii = i + 2 + lw;
            if (ii < total){
                const int rsel = (ii >= len0);
                const int t    = ii - (rsel ? len0 : 0);
                const int bb   = rsel ? b1 : b0;
                pf = ((const float4*)(g_ub + (bb*TT + t)*EE))[lane];
                hav = true;
            }
        }
        {
            const int rsel = (i >= len0);
            const int t    = i - (rsel ? len0 : 0);
            g_xg[((rsel ? b1 : b0)*TT + t)*G3 + j] = dot_s(w, s_ub + (i & 3)*EE) + bi;
        }
        if (i + 1 < total){
            const int rsel = (i + 1 >= len0);
            const int t    = (i + 1) - (rsel ? len0 : 0);
            g_xg[((rsel ? b1 : b0)*TT + t)*G3 + j] = dot_s(w, s_ub + ((i + 1) & 3)*EE) + bi;
        }
        if (hav)
            ((float4*)(s_ub + ((i + 2 + lw) & 3)*EE))[lane] = pf;
        __syncthreads();
    }
}

// ---------------------------------------------------------------------------
// K3: scan only (R12 phase-C code). Same singles+pairs mapping.
// xg read via early-issued __ldg (consumed ~1000 cyc later, latency hidden).
// ---------------------------------------------------------------------------
__global__ void __launch_bounds__(384,1) k_scan(
    const float* __restrict__ W_hh,
    const float* __restrict__ b_hh,
    const float* __restrict__ h0,
    const int*   __restrict__ lens,
    float*       __restrict__ out)
{
    __shared__ __align__(16) float s_h[2*EE];
    __shared__ float s_srz[512];

    const int j   = threadIdx.x;
    const int bid = blockIdx.x;
    const bool dual = (bid >= NS);
    const int b0 = bid;
    const int b1 = dual ? (255 + NS - bid) : bid;
    const int len0 = __ldg(lens + b0);
    const int len1 = dual ? __ldg(lens + b1) : 0;

    u64 w[64];
    {
        const u64* wr = (const u64*)(W_hh + j*EE);
        #pragma unroll
        for (int k = 0; k < 64; ++k) w[k] = __ldg(wr + k);
    }
    const float bh = __ldg(b_hh + j);

    if (j < EE){
        s_h[j]      = __ldg(h0 + b0*EE + j);
        s_h[EE + j] = dual ? __ldg(h0 + b1*EE + j) : 0.f;
    }
    __syncthreads();

    for (int t = 0; t < len0; ++t){
        const bool a1 = (t < len1);
        // issue xg loads first: consumed after the dots + barrier (hidden)
        const float xg0 = __ldg(&g_xg[(b0*TT + t)*G3 + j]);
        float xg1 = 0.f;
        if (a1) xg1 = __ldg(&g_xg[(b1*TT + t)*G3 + j]);

        const float hg0 = dot_s(w, s_h) + bh;
        float hg1 = 0.f;
        if (a1) hg1 = dot_s(w, s_h + EE) + bh;

        if (j < 256){
            s_srz[j]       = hg0 + xg0;
            s_srz[256 + j] = hg1 + xg1;
        }
        __syncthreads();

        if (j >= 256){
            const int e = j - 256;
            {   // row 0 gates (always active: t < len0)
                const float r  = sigf(s_srz[e]);
                const float z  = sigf(s_srz[e + 128]);
                const float n  = tanhfast(xg0 + r * hg0);    // xn + r*hn
                const float hv = (1.f - z)*n + z * s_h[e];
                s_h[e] = hv;
                out[(b0*TT + t)*EE + e] = hv;
            }
            if (a1){
                const float r  = sigf(s_srz[256 + e]);
                const float z  = sigf(s_srz[384 + e]);
                const float n  = tanhfast(xg1 + r * hg1);
                const float hv = (1.f - z)*n + z * s_h[EE + e];
                s_h[EE + e] = hv;
                out[(b1*TT + t)*EE + e] = hv;
            }
        }
        __syncthreads();
    }

    // ---------------- epilogue: masked tail zeros + h_u ----------------
    {
        const float4 z4 = make_float4(0.f, 0.f, 0.f, 0.f);
        float4* p0 = (float4*)(out + (b0*TT + len0)*EE);
        const int n0 = (TT - len0) * (EE/4);
        for (int k = j; k < n0; k += 384) p0[k] = z4;
        if (dual){
            float4* p1 = (float4*)(out + (b1*TT + len1)*EE);
            const int n1 = (TT - len1) * (EE/4);
            for (int k = j; k < n1; k += 384) p1[k] = z4;
        }
    }
    if (j < EE)
        out[BB*TT*EE + b0*EE + j] = s_h[j];
    else if (dual && j < 256)
        out[BB*TT*EE + b1*EE + (j - EE)] = s_h[j];
}

// ---------------------------------------------------------------------------
extern "C" void kernel_launch(void* const* d_in, const int* in_sizes, int n_in,
                              void* d_out, int out_size){
    const int*   item_ids = (const int*)  d_in[0];
    const int*   bsz      = (const int*)  d_in[1];
    const int*   lengths  = (const int*)  d_in[2];
    const float* emb      = (const float*)d_in[3];
    const float* W_ih     = (const float*)d_in[4];
    const float* W_hh     = (const float*)d_in[5];
    const float* b_ih     = (const float*)d_in[6];
    const float* b_hh     = (const float*)d_in[7];
    const float* h0       = (const float*)d_in[8];
    float* out = (float*)d_out;

    k_gather<<<1600, 128>>>(item_ids, bsz, lengths, emb);
    k_xg   <<<GRID, 384>>>(W_ih, b_ih, lengths);
    k_scan <<<GRID, 384>>>(W_hh, b_hh, h0, lengths, out);
}

// round 14
// speedup vs baseline: 1.0695x; 1.0695x over previous
#include <cuda_runtime.h>

#define BB 256
#define TT 50
#define MM 20
#define EE 128
#define G3 384
#define NS 40            // single-row CTAs (longest rows)
#define GRID 148         // NS + (256-NS)/2

typedef unsigned long long u64;

// scratch (no cudaMalloc allowed)
__device__ __align__(16) float g_ub[BB*TT*EE];   // basket means (B,T,E)

__device__ __forceinline__ void fma2(u64 &acc, u64 a, u64 b){
    asm("fma.rn.f32x2 %0, %1, %2, %0;" : "+l"(acc) : "l"(a), "l"(b));
}
__device__ __forceinline__ u64 add2(u64 a, u64 b){
    u64 r; asm("add.rn.f32x2 %0, %1, %2;" : "=l"(r) : "l"(a), "l"(b));
    return r;
}
__device__ __forceinline__ float hsum2(u64 v){
    float lo, hi;
    asm("mov.b64 {%0,%1}, %2;" : "=f"(lo), "=f"(hi) : "l"(v));
    return lo + hi;
}
__device__ __forceinline__ float tanh_hw(float x){
    float y; asm("tanh.approx.f32 %0, %1;" : "=f"(y) : "f"(x));
    return y;
}
__device__ __forceinline__ float sigf(float x){          // 1 MUFU
    return 0.5f + 0.5f * tanh_hw(0.5f * x);
}
__device__ __forceinline__ int zero_dep(float x){
    int r;
    asm("{\n\t.reg .b32 t;\n\tmov.b32 t, %1;\n\tand.b32 %0, t, 0;\n\t}"
        : "=r"(r) : "f"(x));
    return r;
}

// dot of this thread's W row with a 128-float vector in SMEM (broadcast LDS)
__device__ __forceinline__ float dot_s(const u64* __restrict__ w,
                                       const float* __restrict__ src){
    u64 ca = 0ull, cb = 0ull;
    const ulonglong2* hp = (const ulonglong2*)src;
    #pragma unroll
    for (int k = 0; k < 32; ++k){
        ulonglong2 v = hp[k];
        fma2(ca, w[2*k  ], v.x);
        fma2(cb, w[2*k+1], v.y);
    }
    return hsum2(add2(ca, cb));
}

// ---------------------------------------------------------------------------
// K1: gather — R4 low-register version (measured 10.9us, 38 regs, occ 48%).
// One WARP per PAIR of rows (p, 12799-p), processed sequentially.
// ---------------------------------------------------------------------------
__device__ __forceinline__ void gather_row(int r, int lane,
                                           const int* __restrict__ ids,
                                           const int* __restrict__ bsz,
                                           const int* __restrict__ lens,
                                           const float4* __restrict__ e4){
    const int b = r / TT;
    const int t = r - b*TT;
    if (t >= __ldg(lens + b)) return;             // uniform per warp

    const int4* ip = (const int4*)(ids + r*MM);   // 20 ids = 5 int4, broadcast
    const int4 i0 = __ldg(ip+0), i1 = __ldg(ip+1), i2 = __ldg(ip+2),
               i3 = __ldg(ip+3), i4 = __ldg(ip+4);

    float4 v[20];
    v[0]=__ldg(e4+i0.x*32+lane);  v[1]=__ldg(e4+i0.y*32+lane);
    v[2]=__ldg(e4+i0.z*32+lane);  v[3]=__ldg(e4+i0.w*32+lane);
    v[4]=__ldg(e4+i1.x*32+lane);  v[5]=__ldg(e4+i1.y*32+lane);
    v[6]=__ldg(e4+i1.z*32+lane);  v[7]=__ldg(e4+i1.w*32+lane);
    v[8]=__ldg(e4+i2.x*32+lane);  v[9]=__ldg(e4+i2.y*32+lane);
    v[10]=__ldg(e4+i2.z*32+lane); v[11]=__ldg(e4+i2.w*32+lane);
    v[12]=__ldg(e4+i3.x*32+lane); v[13]=__ldg(e4+i3.y*32+lane);
    v[14]=__ldg(e4+i3.z*32+lane); v[15]=__ldg(e4+i3.w*32+lane);
    v[16]=__ldg(e4+i4.x*32+lane); v[17]=__ldg(e4+i4.y*32+lane);
    v[18]=__ldg(e4+i4.z*32+lane); v[19]=__ldg(e4+i4.w*32+lane);

    float4 a;
    a.x = (((v[0].x+v[1].x)+(v[2].x+v[3].x))+((v[4].x+v[5].x)+(v[6].x+v[7].x)))
        + (((v[8].x+v[9].x)+(v[10].x+v[11].x))+((v[12].x+v[13].x)+(v[14].x+v[15].x)))
        + ((v[16].x+v[17].x)+(v[18].x+v[19].x));
    a.y = (((v[0].y+v[1].y)+(v[2].y+v[3].y))+((v[4].y+v[5].y)+(v[6].y+v[7].y)))
        + (((v[8].y+v[9].y)+(v[10].y+v[11].y))+((v[12].y+v[13].y)+(v[14].y+v[15].y)))
        + ((v[16].y+v[17].y)+(v[18].y+v[19].y));
    a.z = (((v[0].z+v[1].z)+(v[2].z+v[3].z))+((v[4].z+v[5].z)+(v[6].z+v[7].z)))
        + (((v[8].z+v[9].z)+(v[10].z+v[11].z))+((v[12].z+v[13].z)+(v[14].z+v[15].z)))
        + ((v[16].z+v[17].z)+(v[18].z+v[19].z));
    a.w = (((v[0].w+v[1].w)+(v[2].w+v[3].w))+((v[4].w+v[5].w)+(v[6].w+v[7].w)))
        + (((v[8].w+v[9].w)+(v[10].w+v[11].w))+((v[12].w+v[13].w)+(v[14].w+v[15].w)))
        + ((v[16].w+v[17].w)+(v[18].w+v[19].w));

    const float inv = 1.0f / (float)__ldg(bsz + r);
    a.x *= inv; a.y *= inv; a.z *= inv; a.w *= inv;
    ((float4*)g_ub)[r*32 + lane] = a;
}

__global__ void __launch_bounds__(256) k_gather(const int* __restrict__ ids,
                                                const int* __restrict__ bsz,
                                                const int* __restrict__ lens,
                                                const float* __restrict__ emb){
    const int p = blockIdx.x * 8 + (threadIdx.x >> 5);   // 0..6399
    const int lane = threadIdx.x & 31;
    const float4* e4 = (const float4*)emb;
    gather_row(p,         lane, ids, bsz, lens, e4);
    gather_row(12799 - p, lane, ids, bsz, lens, e4);
}

// ---------------------------------------------------------------------------
// K2: fused xg + scan (R12 champion). Singles+pairs scheduling:
//   bid <  NS : single row  b0 = bid              (len1 = 0)
//   bid >= NS : pair  b0 = bid, b1 = 255+NS-bid
// Phase B: flat job list, quad-buffered smem staging, 2 dots per barrier.
// Phase C: dual conditional dots, srz via smem, HW-tanh gates, 2 bars/step.
// SMEM: xg 2*50*384 + ub 4*128 + h 2*128 + srz 512 = 39680 fl = 158720 B
// ---------------------------------------------------------------------------
__global__ void __launch_bounds__(384,1) k_xgscan(
    const float* __restrict__ W_ih,
    const float* __restrict__ W_hh,
    const float* __restrict__ b_ih,
    const float* __restrict__ b_hh,
    const float* __restrict__ h0,
    const int*   __restrict__ lens,
    float*       __restrict__ out)
{
    extern __shared__ float smem[];
    float* s_xg  = smem;                   // [2][TT][G3]
    float* s_ub  = s_xg + 2*TT*G3;         // [4][EE] quad buffer
    float* s_h   = s_ub + 4*EE;            // [2][EE]
    float* s_srz = s_h + 2*EE;             // [512]

    const int j   = threadIdx.x;
    const int bid = blockIdx.x;
    const bool dual = (bid >= NS);
    const int b0 = bid;
    const int b1 = dual ? (255 + NS - bid) : bid;
    const int len0 = __ldg(lens + b0);
    const int len1 = dual ? __ldg(lens + b1) : 0;
    const int total = len0 + len1;

    u64 w[64];

    // ---------------- Phase B: xg -> SMEM, flat job list ----------------
    {
        const u64* wr = (const u64*)(W_ih + j*EE);
        #pragma unroll
        for (int k = 0; k < 64; ++k) w[k] = __ldg(wr + k);
    }
    const float bi = __ldg(b_ih + j);
    const int lane = j & 31, lw = j >> 5;

    if (lw < 2 && lw < total){                   // preload jobs 0,1
        const int rsel = (lw >= len0);
        const int t    = lw - (rsel ? len0 : 0);
        const int bb   = rsel ? b1 : b0;
        ((float4*)(s_ub + (lw & 3)*EE))[lane] =
            ((const float4*)(g_ub + (bb*TT + t)*EE))[lane];
    }
    __syncthreads();

    for (int i = 0; i < total; i += 2){
        float4 pf; bool hav = false;
        if (lw < 2){
            const int ii = i + 2 + lw;
            if (ii < total){
                const int rsel = (ii >= len0);
                const int t    = ii - (rsel ? len0 : 0);
                const int bb   = rsel ? b1 : b0;
                pf = ((const float4*)(g_ub + (bb*TT + t)*EE))[lane];
                hav = true;
            }
        }
        {
            const int rsel = (i >= len0);
            const int t    = i - (rsel ? len0 : 0);
            s_xg[(rsel*TT + t)*G3 + j] = dot_s(w, s_ub + (i & 3)*EE) + bi;
        }
        if (i + 1 < total){
            const int rsel = (i + 1 >= len0);
            const int t    = (i + 1) - (rsel ? len0 : 0);
            s_xg[(rsel*TT + t)*G3 + j] = dot_s(w, s_ub + ((i + 1) & 3)*EE) + bi;
        }
        if (hav)
            ((float4*)(s_ub + ((i + 2 + lw) & 3)*EE))[lane] = pf;
        __syncthreads();
    }

    // ---------------- Phase C: scan ----------------
    const int dep = zero_dep(s_xg[j]);           // keep W_hh load after phase B
    {
        const u64* wr = (const u64*)(W_hh + (j + dep)*EE);
        #pragma unroll
        for (int k = 0; k < 64; ++k) w[k] = __ldg(wr + k);
    }
    const float bh = __ldg(b_hh + j);

    if (j < EE){
        s_h[j]      = __ldg(h0 + b0*EE + j);
        s_h[EE + j] = dual ? __ldg(h0 + b1*EE + j) : 0.f;
    }
    __syncthreads();

    for (int t = 0; t < len0; ++t){
        const bool a1 = (t < len1);
        const float xg0 = s_xg[t*G3 + j];
        const float hg0 = dot_s(w, s_h) + bh;
        float xg1 = 0.f, hg1 = 0.f;
        if (a1){ xg1 = s_xg[(TT + t)*G3 + j]; hg1 = dot_s(w, s_h + EE) + bh; }

        if (j < 256){
            s_srz[j]       = hg0 + xg0;
            s_srz[256 + j] = hg1 + xg1;
        }
        __syncthreads();

        if (j >= 256){
            const int e = j - 256;
            {   // row 0 gates (always active: t < len0)
                const float r  = sigf(s_srz[e]);
                const float z  = sigf(s_srz[e + 128]);
                const float n  = tanh_hw(xg0 + r * hg0);     // xn + r*hn
                const float hv = z*(s_h[e] - n) + n;
                s_h[e] = hv;
                out[(b0*TT + t)*EE + e] = hv;
            }
            if (a1){
                const float r  = sigf(s_srz[256 + e]);
                const float z  = sigf(s_srz[384 + e]);
                const float n  = tanh_hw(xg1 + r * hg1);
                const float hv = z*(s_h[EE + e] - n) + n;
                s_h[EE + e] = hv;
                out[(b1*TT + t)*EE + e] = hv;
            }
        }
        __syncthreads();
    }

    // ---------------- epilogue: masked tail zeros + h_u ----------------
    {
        const float4 z4 = make_float4(0.f, 0.f, 0.f, 0.f);
        float4* p0 = (float4*)(out + (b0*TT + len0)*EE);
        const int n0 = (TT - len0) * (EE/4);
        for (int k = j; k < n0; k += 384) p0[k] = z4;
        if (dual){
            float4* p1 = (float4*)(out + (b1*TT + len1)*EE);
            const int n1 = (TT - len1) * (EE/4);
            for (int k = j; k < n1; k += 384) p1[k] = z4;
        }
    }
    if (j < EE)
        out[BB*TT*EE + b0*EE + j] = s_h[j];
    else if (dual && j < 256)
        out[BB*TT*EE + b1*EE + (j - EE)] = s_h[j];
}

// ---------------------------------------------------------------------------
extern "C" void kernel_launch(void* const* d_in, const int* in_sizes, int n_in,
                              void* d_out, int out_size){
    const int*   item_ids = (const int*)  d_in[0];
    const int*   bsz      = (const int*)  d_in[1];
    const int*   lengths  = (const int*)  d_in[2];
    const float* emb      = (const float*)d_in[3];
    const float* W_ih     = (const float*)d_in[4];
    const float* W_hh     = (const float*)d_in[5];
    const float* b_ih     = (const float*)d_in[6];
    const float* b_hh     = (const float*)d_in[7];
    const float* h0       = (const float*)d_in[8];
    float* out = (float*)d_out;

    const int smem_bytes = (2*TT*G3 + 4*EE + 2*EE + 512) * 4;   // 158720
    cudaFuncSetAttribute(k_xgscan, cudaFuncAttributeMaxDynamicSharedMemorySize,
                         smem_bytes);

    k_gather<<<800, 256>>>(item_ids, bsz, lengths, emb);
    k_xgscan<<<GRID, 384, smem_bytes>>>(W_ih, W_hh, b_ih, b_hh, h0,
                                        lengths, out);
}

// round 15
// speedup vs baseline: 1.1270x; 1.0537x over previous
#include <cuda_runtime.h>

#define BB 256
#define TT 50
#define MM 20
#define EE 128
#define G3 384
#define NS 40            // single-row CTAs (longest rows)
#define GRID 148         // NS + (256-NS)/2

typedef unsigned long long u64;

// scratch (no cudaMalloc allowed)
__device__ __align__(16) float g_ub[BB*TT*EE];   // basket means (B,T,E)

__device__ __forceinline__ void fma2(u64 &acc, u64 a, u64 b){
    asm("fma.rn.f32x2 %0, %1, %2, %0;" : "+l"(acc) : "l"(a), "l"(b));
}
__device__ __forceinline__ u64 add2(u64 a, u64 b){
    u64 r; asm("add.rn.f32x2 %0, %1, %2;" : "=l"(r) : "l"(a), "l"(b));
    return r;
}
__device__ __forceinline__ float hsum2(u64 v){
    float lo, hi;
    asm("mov.b64 {%0,%1}, %2;" : "=f"(lo), "=f"(hi) : "l"(v));
    return lo + hi;
}
__device__ __forceinline__ float tanh_hw(float x){
    float y; asm("tanh.approx.f32 %0, %1;" : "=f"(y) : "f"(x));
    return y;
}
__device__ __forceinline__ float sigf(float x){          // 1 MUFU
    return 0.5f + 0.5f * tanh_hw(0.5f * x);
}
__device__ __forceinline__ int zero_dep(float x){
    int r;
    asm("{\n\t.reg .b32 t;\n\tmov.b32 t, %1;\n\tand.b32 %0, t, 0;\n\t}"
        : "=r"(r) : "f"(x));
    return r;
}

// dot of this thread's W row with a 128-float vector in SMEM (broadcast LDS)
__device__ __forceinline__ float dot_s(const u64* __restrict__ w,
                                       const float* __restrict__ src){
    u64 ca = 0ull, cb = 0ull;
    const ulonglong2* hp = (const ulonglong2*)src;
    #pragma unroll
    for (int k = 0; k < 32; ++k){
        ulonglong2 v = hp[k];
        fma2(ca, w[2*k  ], v.x);
        fma2(cb, w[2*k+1], v.y);
    }
    return hsum2(add2(ca, cb));
}

// ---------------------------------------------------------------------------
// K1: gather — R4 low-register version (measured ~11us, occ 48%).
// One WARP per PAIR of rows (p, 12799-p), processed sequentially.
// ---------------------------------------------------------------------------
__device__ __forceinline__ void gather_row(int r, int lane,
                                           const int* __restrict__ ids,
                                           const int* __restrict__ bsz,
                                           const int* __restrict__ lens,
                                           const float4* __restrict__ e4){
    const int b = r / TT;
    const int t = r - b*TT;
    if (t >= __ldg(lens + b)) return;             // uniform per warp

    const int4* ip = (const int4*)(ids + r*MM);   // 20 ids = 5 int4, broadcast
    const int4 i0 = __ldg(ip+0), i1 = __ldg(ip+1), i2 = __ldg(ip+2),
               i3 = __ldg(ip+3), i4 = __ldg(ip+4);

    float4 v[20];
    v[0]=__ldg(e4+i0.x*32+lane);  v[1]=__ldg(e4+i0.y*32+lane);
    v[2]=__ldg(e4+i0.z*32+lane);  v[3]=__ldg(e4+i0.w*32+lane);
    v[4]=__ldg(e4+i1.x*32+lane);  v[5]=__ldg(e4+i1.y*32+lane);
    v[6]=__ldg(e4+i1.z*32+lane);  v[7]=__ldg(e4+i1.w*32+lane);
    v[8]=__ldg(e4+i2.x*32+lane);  v[9]=__ldg(e4+i2.y*32+lane);
    v[10]=__ldg(e4+i2.z*32+lane); v[11]=__ldg(e4+i2.w*32+lane);
    v[12]=__ldg(e4+i3.x*32+lane); v[13]=__ldg(e4+i3.y*32+lane);
    v[14]=__ldg(e4+i3.z*32+lane); v[15]=__ldg(e4+i3.w*32+lane);
    v[16]=__ldg(e4+i4.x*32+lane); v[17]=__ldg(e4+i4.y*32+lane);
    v[18]=__ldg(e4+i4.z*32+lane); v[19]=__ldg(e4+i4.w*32+lane);

    float4 a;
    a.x = (((v[0].x+v[1].x)+(v[2].x+v[3].x))+((v[4].x+v[5].x)+(v[6].x+v[7].x)))
        + (((v[8].x+v[9].x)+(v[10].x+v[11].x))+((v[12].x+v[13].x)+(v[14].x+v[15].x)))
        + ((v[16].x+v[17].x)+(v[18].x+v[19].x));
    a.y = (((v[0].y+v[1].y)+(v[2].y+v[3].y))+((v[4].y+v[5].y)+(v[6].y+v[7].y)))
        + (((v[8].y+v[9].y)+(v[10].y+v[11].y))+((v[12].y+v[13].y)+(v[14].y+v[15].y)))
        + ((v[16].y+v[17].y)+(v[18].y+v[19].y));
    a.z = (((v[0].z+v[1].z)+(v[2].z+v[3].z))+((v[4].z+v[5].z)+(v[6].z+v[7].z)))
        + (((v[8].z+v[9].z)+(v[10].z+v[11].z))+((v[12].z+v[13].z)+(v[14].z+v[15].z)))
        + ((v[16].z+v[17].z)+(v[18].z+v[19].z));
    a.w = (((v[0].w+v[1].w)+(v[2].w+v[3].w))+((v[4].w+v[5].w)+(v[6].w+v[7].w)))
        + (((v[8].w+v[9].w)+(v[10].w+v[11].w))+((v[12].w+v[13].w)+(v[14].w+v[15].w)))
        + ((v[16].w+v[17].w)+(v[18].w+v[19].w));

    const float inv = 1.0f / (float)__ldg(bsz + r);
    a.x *= inv; a.y *= inv; a.z *= inv; a.w *= inv;
    ((float4*)g_ub)[r*32 + lane] = a;
}

__global__ void __launch_bounds__(256) k_gather(const int* __restrict__ ids,
                                                const int* __restrict__ bsz,
                                                const int* __restrict__ lens,
                                                const float* __restrict__ emb){
    const int p = blockIdx.x * 8 + (threadIdx.x >> 5);   // 0..6399
    const int lane = threadIdx.x & 31;
    const float4* e4 = (const float4*)emb;
    gather_row(p,         lane, ids, bsz, lens, e4);
    gather_row(12799 - p, lane, ids, bsz, lens, e4);
}

// ---------------------------------------------------------------------------
// K2: fused xg + scan. Singles+pairs scheduling:
//   bid <  NS : single row  b0 = bid              (len1 = 0)
//   bid >= NS : pair  b0 = bid, b1 = 255+NS-bid
// Phase B: flat job list, 8-slot ub ring, 4 dots per barrier.
// Phase C: dual conditional dots -> all threads STS hg -> 256 threads compute
//          ONE gate element each (all inputs from smem). 2 barriers/step.
// SMEM: xg 2*50*384 + ub 8*128 + h 2*128 + hg 2*384 = 40448 fl = 161792 B
// ---------------------------------------------------------------------------
__global__ void __launch_bounds__(384,1) k_xgscan(
    const float* __restrict__ W_ih,
    const float* __restrict__ W_hh,
    const float* __restrict__ b_ih,
    const float* __restrict__ b_hh,
    const float* __restrict__ h0,
    const int*   __restrict__ lens,
    float*       __restrict__ out)
{
    extern __shared__ float smem[];
    float* s_xg = smem;                    // [2][TT][G3]
    float* s_ub = s_xg + 2*TT*G3;          // [8][EE] ring buffer
    float* s_h  = s_ub + 8*EE;             // [2][EE]
    float* s_hg = s_h + 2*EE;              // [2][G3]

    const int j   = threadIdx.x;
    const int bid = blockIdx.x;
    const bool dual = (bid >= NS);
    const int b0 = bid;
    const int b1 = dual ? (255 + NS - bid) : bid;
    const int len0 = __ldg(lens + b0);
    const int len1 = dual ? __ldg(lens + b1) : 0;
    const int total = len0 + len1;

    u64 w[64];

    // ---------------- Phase B: xg -> SMEM, flat job list, 4/barrier ------
    {
        const u64* wr = (const u64*)(W_ih + j*EE);
        #pragma unroll
        for (int k = 0; k < 64; ++k) w[k] = __ldg(wr + k);
    }
    const float bi = __ldg(b_ih + j);
    const int lane = j & 31, lw = j >> 5;

    if (lw < 4 && lw < total){                   // preload jobs 0..3
        const int rsel = (lw >= len0);
        const int t    = lw - (rsel ? len0 : 0);
        const int bb   = rsel ? b1 : b0;
        ((float4*)(s_ub + (lw & 7)*EE))[lane] =
            ((const float4*)(g_ub + (bb*TT + t)*EE))[lane];
    }
    __syncthreads();

    for (int i = 0; i < total; i += 4){
        float4 pf; bool hav = false;
        if (lw < 4){
            const int ii = i + 4 + lw;
            if (ii < total){
                const int rsel = (ii >= len0);
                const int t    = ii - (rsel ? len0 : 0);
                const int bb   = rsel ? b1 : b0;
                pf = ((const float4*)(g_ub + (bb*TT + t)*EE))[lane];
                hav = true;
            }
        }
        #pragma unroll
        for (int u = 0; u < 4; ++u){
            const int ii = i + u;
            if (ii < total){
                const int rsel = (ii >= len0);
                const int t    = ii - (rsel ? len0 : 0);
                s_xg[(rsel*TT + t)*G3 + j] = dot_s(w, s_ub + (ii & 7)*EE) + bi;
            }
        }
        if (hav)
            ((float4*)(s_ub + ((i + 4 + lw) & 7)*EE))[lane] = pf;
        __syncthreads();
    }

    // ---------------- Phase C: scan ----------------
    const int dep = zero_dep(s_xg[j]);           // keep W_hh load after phase B
    {
        const u64* wr = (const u64*)(W_hh + (j + dep)*EE);
        #pragma unroll
        for (int k = 0; k < 64; ++k) w[k] = __ldg(wr + k);
    }
    const float bh = __ldg(b_hh + j);

    if (j < EE){
        s_h[j]      = __ldg(h0 + b0*EE + j);
        s_h[EE + j] = dual ? __ldg(h0 + b1*EE + j) : 0.f;
    }
    __syncthreads();

    for (int t = 0; t < len0; ++t){
        const bool a1 = (t < len1);
        const float hg0 = dot_s(w, s_h) + bh;
        float hg1 = 0.f;
        if (a1) hg1 = dot_s(w, s_h + EE) + bh;

        s_hg[j]      = hg0;
        s_hg[G3 + j] = hg1;
        __syncthreads();

        if (j < 256){
            const int row = j >> 7, e = j & 127;
            if (row == 0 || a1){
                const float* xr = s_xg + (row*TT + t)*G3;
                const float* hp = s_hg + row*G3;
                const float r  = sigf(xr[e]       + hp[e]);
                const float z  = sigf(xr[e + 128] + hp[e + 128]);
                const float n  = tanh_hw(xr[e + 256] + r * hp[e + 256]);
                const float hv = z*(s_h[row*EE + e] - n) + n;
                s_h[row*EE + e] = hv;
                out[((row ? b1 : b0)*TT + t)*EE + e] = hv;
            }
        }
        __syncthreads();
    }

    // ---------------- epilogue: masked tail zeros + h_u ----------------
    {
        const float4 z4 = make_float4(0.f, 0.f, 0.f, 0.f);
        float4* p0 = (float4*)(out + (b0*TT + len0)*EE);
        const int n0 = (TT - len0) * (EE/4);
        for (int k = j; k < n0; k += 384) p0[k] = z4;
        if (dual){
            float4* p1 = (float4*)(out + (b1*TT + len1)*EE);
            const int n1 = (TT - len1) * (EE/4);
            for (int k = j; k < n1; k += 384) p1[k] = z4;
        }
    }
    if (j < EE)
        out[BB*TT*EE + b0*EE + j] = s_h[j];
    else if (dual && j < 256)
        out[BB*TT*EE + b1*EE + (j - EE)] = s_h[j];
}

// ---------------------------------------------------------------------------
extern "C" void kernel_launch(void* const* d_in, const int* in_sizes, int n_in,
                              void* d_out, int out_size){
    const int*   item_ids = (const int*)  d_in[0];
    const int*   bsz      = (const int*)  d_in[1];
    const int*   lengths  = (const int*)  d_in[2];
    const float* emb      = (const float*)d_in[3];
    const float* W_ih     = (const float*)d_in[4];
    const float* W_hh     = (const float*)d_in[5];
    const float* b_ih     = (const float*)d_in[6];
    const float* b_hh     = (const float*)d_in[7];
    const float* h0       = (const float*)d_in[8];
    float* out = (float*)d_out;

    const int smem_bytes = (2*TT*G3 + 8*EE + 2*EE + 2*G3) * 4;   // 161792
    cudaFuncSetAttribute(k_xgscan, cudaFuncAttributeMaxDynamicSharedMemorySize,
                         smem_bytes);

    k_gather<<<800, 256>>>(item_ids, bsz, lengths, emb);
    k_xgscan<<<GRID, 384, smem_bytes>>>(W_ih, W_hh, b_ih, b_hh, h0,
                                        lengths, out);
}